// round 8
// baseline (speedup 1.0000x reference)
#include <cuda_runtime.h>
#include <cuda_bf16.h>
#include <stdint.h>

#define DIM     1024
#define HEADS   8
#define DH      64
#define NSEQ    4096
#define BATCH   2
#define TOKENS  (BATCH*NSEQ)     // 8192
#define QKV_N   (3*HEADS*DH)     // 1536
#define AO_N    (HEADS*DH)       // 512
#define BH_N    (BATCH*HEADS)    // 16
#define QSCALE  0.18033688011112042f   // 0.125 * log2(e)

// ===================== scratch globals =======================================
__device__ __align__(16) __nv_bfloat16 g_xn_hi[TOKENS * DIM];
__device__ __align__(16) __nv_bfloat16 g_xn_lo[TOKENS * DIM];
__device__ __align__(16) __nv_bfloat16 g_wq_hi[QKV_N * DIM];   // [1536,1024] K-major
__device__ __align__(16) __nv_bfloat16 g_wq_lo[QKV_N * DIM];
__device__ __align__(16) __nv_bfloat16 g_wo_hi[DIM * AO_N];    // [1024,512]  K-major
__device__ __align__(16) __nv_bfloat16 g_wo_lo[DIM * AO_N];
__device__ __align__(16) __nv_bfloat16 g_qh[BH_N * NSEQ * DH]; // head-major, log2-scaled
__device__ __align__(16) __nv_bfloat16 g_ql[BH_N * NSEQ * DH];
__device__ __align__(16) __nv_bfloat16 g_kh[BH_N * NSEQ * DH];
__device__ __align__(16) __nv_bfloat16 g_kl[BH_N * NSEQ * DH];
__device__ __align__(16) __nv_bfloat16 g_vh[BH_N * NSEQ * DH];
__device__ __align__(16) __nv_bfloat16 g_vl[BH_N * NSEQ * DH];
__device__ __align__(16) __nv_bfloat16 g_ao_hi[TOKENS * AO_N];
__device__ __align__(16) __nv_bfloat16 g_ao_lo[TOKENS * AO_N];

// ===================== PTX helpers (portable, sm_80+) ========================
__device__ __forceinline__ uint32_t smem_u32(const void* p) {
    uint32_t a;
    asm("{ .reg .u64 t; cvta.to.shared.u64 t, %1; cvt.u32.u64 %0, t; }"
        : "=r"(a) : "l"(p));
    return a;
}
__device__ __forceinline__ void cp16(uint32_t dst, const void* src) {
    asm volatile("cp.async.cg.shared.global [%0], [%1], 16;"
                 :: "r"(dst), "l"(src));
}
#define CP_COMMIT() asm volatile("cp.async.commit_group;" ::: "memory")
#define CP_WAIT1()  asm volatile("cp.async.wait_group 1;"  ::: "memory")

__device__ __forceinline__ void ldsm4(uint32_t (&r)[4], uint32_t a) {
    asm volatile("ldmatrix.sync.aligned.m8n8.x4.shared.b16 {%0,%1,%2,%3}, [%4];"
        : "=r"(r[0]), "=r"(r[1]), "=r"(r[2]), "=r"(r[3]) : "r"(a));
}
__device__ __forceinline__ void ldsm4t(uint32_t (&r)[4], uint32_t a) {
    asm volatile("ldmatrix.sync.aligned.m8n8.x4.trans.shared.b16 {%0,%1,%2,%3}, [%4];"
        : "=r"(r[0]), "=r"(r[1]), "=r"(r[2]), "=r"(r[3]) : "r"(a));
}
__device__ __forceinline__ void mma16816(float (&d)[4], const uint32_t (&a)[4],
                                         uint32_t b0, uint32_t b1) {
    asm volatile(
        "mma.sync.aligned.m16n8k16.row.col.f32.bf16.bf16.f32 "
        "{%0,%1,%2,%3}, {%4,%5,%6,%7}, {%8,%9}, {%0,%1,%2,%3};"
        : "+f"(d[0]), "+f"(d[1]), "+f"(d[2]), "+f"(d[3])
        : "r"(a[0]), "r"(a[1]), "r"(a[2]), "r"(a[3]), "r"(b0), "r"(b1));
}
__device__ __forceinline__ float ex2(float x) {
    float y;
    asm("ex2.approx.f32 %0, %1;" : "=f"(y) : "f"(x));
    return y;
}
__device__ __forceinline__ void pack_split(float x0, float x1,
                                           uint32_t& ph, uint32_t& pl) {
    uint32_t hp;
    asm("cvt.rn.bf16x2.f32 %0, %1, %2;" : "=r"(hp) : "f"(x1), "f"(x0));
    __nv_bfloat162 hv = *reinterpret_cast<__nv_bfloat162*>(&hp);
    float r0 = x0 - __bfloat162float(hv.x);
    float r1 = x1 - __bfloat162float(hv.y);
    asm("cvt.rn.bf16x2.f32 %0, %1, %2;" : "=r"(pl) : "f"(r1), "f"(r0));
    ph = hp;
}
// 128-byte-row XOR swizzle (16B chunks)
__device__ __forceinline__ uint32_t sw128(int r, int cb) {
    return (uint32_t)(r * 128 + ((((cb >> 4) ^ (r & 7))) << 4));
}

// ===================== 1) fused prep: LN + both weight converts ==============
#define CONV0_BLKS ((QKV_N / 32) * (DIM / 32))   // 1536
#define CONV1_BLKS ((DIM / 32) * (AO_N / 32))    // 512
__global__ void prep_kernel(const float* __restrict__ x,
                            const float* __restrict__ gamma,
                            const float* __restrict__ beta,
                            const float* __restrict__ wqkv,
                            const float* __restrict__ wout) {
    const int blk = blockIdx.x;
    const int tid = threadIdx.x;
    if (blk < TOKENS) {
        // ---- LayerNorm -> bf16 hi/lo ----
        const int t = blk;
        const float4 v = *(const float4*)(x + (size_t)t * DIM + tid * 4);
        float s  = v.x + v.y + v.z + v.w;
        float s2 = v.x*v.x + v.y*v.y + v.z*v.z + v.w*v.w;
        #pragma unroll
        for (int o = 16; o > 0; o >>= 1) {
            s  += __shfl_down_sync(0xffffffffu, s,  o);
            s2 += __shfl_down_sync(0xffffffffu, s2, o);
        }
        __shared__ float ws[8], ws2[8];
        __shared__ float s_mu, s_rstd;
        const int wid = tid >> 5, lane = tid & 31;
        if (lane == 0) { ws[wid] = s; ws2[wid] = s2; }
        __syncthreads();
        if (tid == 0) {
            float S = 0.f, S2 = 0.f;
            #pragma unroll
            for (int i = 0; i < 8; i++) { S += ws[i]; S2 += ws2[i]; }
            float mu  = S * (1.0f / DIM);
            float var = S2 * (1.0f / DIM) - mu * mu;
            s_mu = mu;
            s_rstd = rsqrtf(var + 1e-5f);
        }
        __syncthreads();
        const float mu = s_mu, rstd = s_rstd;
        const float4 g = *(const float4*)(gamma + tid * 4);
        const float4 b = *(const float4*)(beta  + tid * 4);
        float y[4];
        y[0] = (v.x - mu) * rstd * g.x + b.x;
        y[1] = (v.y - mu) * rstd * g.y + b.y;
        y[2] = (v.z - mu) * rstd * g.z + b.z;
        y[3] = (v.w - mu) * rstd * g.w + b.w;
        const size_t o = (size_t)t * DIM + tid * 4;
        uint32_t h0, l0, h1, l1;
        pack_split(y[0], y[1], h0, l0);
        pack_split(y[2], y[3], h1, l1);
        *(uint32_t*)(g_xn_hi + o)     = h0;
        *(uint32_t*)(g_xn_hi + o + 2) = h1;
        *(uint32_t*)(g_xn_lo + o)     = l0;
        *(uint32_t*)(g_xn_lo + o + 2) = l1;
    } else {
        // ---- weight transpose + bf16 split ----
        __shared__ float tbuf[32][33];
        int idx, Kd, Nd;
        const float* src;
        __nv_bfloat16 *hi, *lo;
        if (blk < TOKENS + CONV0_BLKS) {
            idx = blk - TOKENS; Kd = DIM; Nd = QKV_N;
            src = wqkv; hi = g_wq_hi; lo = g_wq_lo;
        } else {
            idx = blk - TOKENS - CONV0_BLKS; Kd = AO_N; Nd = DIM;
            src = wout; hi = g_wo_hi; lo = g_wo_lo;
        }
        const int nb = Nd / 32;
        const int n0 = (idx % nb) * 32, k0 = (idx / nb) * 32;
        const int tx = tid & 31, ty = tid >> 5;
        #pragma unroll
        for (int i = ty; i < 32; i += 8)
            tbuf[i][tx] = src[(size_t)(k0 + i) * Nd + n0 + tx];
        __syncthreads();
        #pragma unroll
        for (int i = ty; i < 32; i += 8) {
            const float v = tbuf[tx][i];
            const __nv_bfloat16 h = __float2bfloat16(v);
            const size_t off = (size_t)(n0 + i) * Kd + k0 + tx;
            hi[off] = h;
            lo[off] = __float2bfloat16(v - __bfloat162float(h));
        }
    }
}

// ===================== 2) bf16x3 mma.sync GEMM, 128x128, 3-stage cp.async ====
#define GSTAGE 32768
__device__ __forceinline__ void gemm_load3(uint32_t sb, int st,
    const __nv_bfloat16* __restrict__ Ah, const __nv_bfloat16* __restrict__ Al,
    const __nv_bfloat16* __restrict__ Bh, const __nv_bfloat16* __restrict__ Bl,
    int m0, int n0, int K, int k0, int tid)
{
    const uint32_t base = sb + st * GSTAGE;
    #pragma unroll
    for (int t = 0; t < 8; t++) {
        const int rc = tid + (t & 3) * 256;     // 0..1023
        const int r = rc >> 3, c = rc & 7;
        const int isB = t >> 2;                 // 0: A, 1: B
        const uint32_t d = base + isB * 16384 + sw128(r, c * 16);
        const int row = (isB ? n0 : m0) + r;
        const __nv_bfloat16* hi = isB ? Bh : Ah;
        const __nv_bfloat16* lo = isB ? Bl : Al;
        const __nv_bfloat16* src = (c < 4)
            ? (hi + (size_t)row * K + k0 + c * 8)
            : (lo + (size_t)row * K + k0 + (c - 4) * 8);
        cp16(d, src);
    }
}

template<int MODE>
__global__ void __launch_bounds__(256, 2) gemm_mma(float* __restrict__ Cout) {
    constexpr int K  = (MODE == 0) ? DIM : AO_N;
    constexpr int NC = K / 32;
    extern __shared__ char dsm[];
    const uint32_t sb = smem_u32(dsm);

    const int tid = threadIdx.x, lane = tid & 31, warp = tid >> 5;
    const int g = lane >> 2, tig = lane & 3;
    const int wm = (warp >> 1) * 32, wn = (warp & 1) * 64;
    const int m0 = blockIdx.y * 128, n0 = blockIdx.x * 128;

    const __nv_bfloat16* __restrict__ Ah = (MODE == 0) ? g_xn_hi : g_ao_hi;
    const __nv_bfloat16* __restrict__ Al = (MODE == 0) ? g_xn_lo : g_ao_lo;
    const __nv_bfloat16* __restrict__ Bh = (MODE == 0) ? g_wq_hi : g_wo_hi;
    const __nv_bfloat16* __restrict__ Bl = (MODE == 0) ? g_wq_lo : g_wo_lo;

    float c[2][8][4] = {};

    gemm_load3(sb, 0, Ah, Al, Bh, Bl, m0, n0, K, 0,  tid);
    CP_COMMIT();
    gemm_load3(sb, 1, Ah, Al, Bh, Bl, m0, n0, K, 32, tid);
    CP_COMMIT();

    int stc = 0, stp = 2;
    for (int cc = 0; cc < NC; cc++) {
        CP_WAIT1();
        __syncthreads();
        if (cc + 2 < NC)
            gemm_load3(sb, stp, Ah, Al, Bh, Bl, m0, n0, K, (cc + 2) * 32, tid);
        CP_COMMIT();

        const uint32_t uA = sb + stc * GSTAGE;
        const uint32_t uB = uA + 16384;

        #pragma unroll
        for (int hh = 0; hh < 2; hh++) {
            const int acb = hh * 32 + (lane >> 4) * 16;
            uint32_t ah[2][4], al[2][4];
            #pragma unroll
            for (int i = 0; i < 2; i++) {
                const int row = wm + i * 16 + (lane & 15);
                ldsm4(ah[i], uA + sw128(row, acb));
                ldsm4(al[i], uA + sw128(row, acb + 64));
            }
            #pragma unroll
            for (int nb = 0; nb < 4; nb++) {
                const int row = wn + nb * 16 + (lane & 7) + ((lane >> 3) & 1) * 8;
                uint32_t bhh[4], bll[4];
                ldsm4(bhh, uB + sw128(row, acb));
                ldsm4(bll, uB + sw128(row, acb + 64));
                mma16816(c[0][nb*2+0], ah[0], bhh[0], bhh[2]);
                mma16816(c[0][nb*2+1], ah[0], bhh[1], bhh[3]);
                mma16816(c[1][nb*2+0], ah[1], bhh[0], bhh[2]);
                mma16816(c[1][nb*2+1], ah[1], bhh[1], bhh[3]);
                mma16816(c[0][nb*2+0], ah[0], bll[0], bll[2]);
                mma16816(c[0][nb*2+1], ah[0], bll[1], bll[3]);
                mma16816(c[1][nb*2+0], ah[1], bll[0], bll[2]);
                mma16816(c[1][nb*2+1], ah[1], bll[1], bll[3]);
                mma16816(c[0][nb*2+0], al[0], bhh[0], bhh[2]);
                mma16816(c[0][nb*2+1], al[0], bhh[1], bhh[3]);
                mma16816(c[1][nb*2+0], al[1], bhh[0], bhh[2]);
                mma16816(c[1][nb*2+1], al[1], bhh[1], bhh[3]);
            }
        }
        stc = (stc == 2) ? 0 : stc + 1;
        stp = (stp == 2) ? 0 : stp + 1;
    }

    if (MODE == 0) {
        #pragma unroll
        for (int i = 0; i < 2; i++) {
            const int r0g = m0 + wm + i * 16 + g;
            #pragma unroll
            for (int j = 0; j < 8; j++) {
                const int col  = n0 + wn + j * 8 + tig * 2;
                const int part = col >> 9;
                const int hd   = (col >> 6) & 7;
                const int d    = col & 63;
                __nv_bfloat16* dh_ = (part == 0) ? g_qh : ((part == 1) ? g_kh : g_vh);
                __nv_bfloat16* dl_ = (part == 0) ? g_ql : ((part == 1) ? g_kl : g_vl);
                const float sc = (part == 0) ? QSCALE : 1.0f;
                #pragma unroll
                for (int rr = 0; rr < 2; rr++) {
                    const int row = r0g + rr * 8;
                    const int bb = row >> 12, seq = row & 4095;
                    const size_t off = (((size_t)(bb * HEADS + hd)) * NSEQ + seq) * DH + d;
                    uint32_t ph, pl;
                    pack_split(c[i][j][rr*2+0] * sc, c[i][j][rr*2+1] * sc, ph, pl);
                    *(uint32_t*)(dh_ + off) = ph;
                    *(uint32_t*)(dl_ + off) = pl;
                }
            }
        }
    } else {
        #pragma unroll
        for (int i = 0; i < 2; i++) {
            const int r0g = m0 + wm + i * 16 + g;
            #pragma unroll
            for (int j = 0; j < 8; j++) {
                const int col = n0 + wn + j * 8 + tig * 2;
                #pragma unroll
                for (int rr = 0; rr < 2; rr++) {
                    const int row = r0g + rr * 8;
                    *(float2*)(Cout + (size_t)row * DIM + col) =
                        make_float2(c[i][j][rr*2+0], c[i][j][rr*2+1]);
                }
            }
        }
    }
}

// ===================== 3) causal flash attention, 3-stage, interleaved =======
#define AST 32768
__device__ __forceinline__ void kv_load(uint32_t sb, int st, size_t kvbase,
                                        int kt, int tid) {
    const int r  = tid >> 2;
    const int c0 = (tid & 3) * 2;
    const uint32_t base = sb + st * AST;
    #pragma unroll
    for (int it = 0; it < 2; it++) {
        const int ch = c0 + it;
        const uint32_t d = base + sw128(r, ch * 16);
        const size_t src = kvbase + (size_t)(kt * 64 + r) * DH + ch * 8;
        cp16(d,         g_kh + src);
        cp16(d + 8192,  g_kl + src);
        cp16(d + 16384, g_vh + src);
        cp16(d + 24576, g_vl + src);
    }
}

__global__ void __launch_bounds__(256, 2) attn_kernel() {
    extern __shared__ char dsm[];
    const uint32_t sb = smem_u32(dsm);
    const int qt = (int)gridDim.x - 1 - (int)blockIdx.x;  // big tiles first
    const int bh = blockIdx.y, b = bh >> 3, h = bh & 7;
    const int tid = threadIdx.x, lane = tid & 31, warp = tid >> 5;
    const int g = lane >> 2, tig = lane & 3;
    const int wm = warp * 16;
    const size_t kvbase = (size_t)bh * NSEQ * DH;

    // ---- stage Q into stage-1/2 areas ----
    const size_t qbase = ((size_t)bh * NSEQ + qt * 128) * DH;
    for (int i = tid; i < 1024; i += 256) {
        const int r = i >> 3, cch = i & 7;
        const uint32_t d = sw128(r, cch * 16);
        const size_t src = qbase + (size_t)r * DH + cch * 8;
        *(uint4*)(dsm + 32768 + d) = *(const uint4*)(g_qh + src);
        *(uint4*)(dsm + 65536 + d) = *(const uint4*)(g_ql + src);
    }
    __syncthreads();
    uint32_t qh[4][4], ql[4][4];
    #pragma unroll
    for (int kk = 0; kk < 4; kk++) {
        const int r  = wm + (lane & 15);
        const int cb = kk * 32 + (lane >> 4) * 16;
        const uint32_t off = sw128(r, cb);
        ldsm4(qh[kk], sb + 32768 + off);
        ldsm4(ql[kk], sb + 65536 + off);
    }
    __syncthreads();

    const int ktmax = 2 * qt + 1;
    kv_load(sb, 0, kvbase, 0, tid);
    CP_COMMIT();
    kv_load(sb, 1, kvbase, 1, tid);
    CP_COMMIT();

    float o[8][4] = {};
    float m0v = -1e30f, m1v = -1e30f, l0 = 0.f, l1 = 0.f;

    int stc = 0, stp = 2;
    for (int kt = 0; kt <= ktmax; kt++) {
        CP_WAIT1();
        __syncthreads();
        if (kt + 2 <= ktmax)
            kv_load(sb, stp, kvbase, kt + 2, tid);
        CP_COMMIT();

        const uint32_t uK  = sb + stc * AST;
        const uint32_t uKl = uK + 8192;
        const uint32_t uV  = uK + 16384;
        const uint32_t uVl = uK + 24576;

        // ---- S = Q K^T (3-term bf16), log2 domain ----
        float s[8][4] = {};
        #pragma unroll
        for (int kk = 0; kk < 4; kk++) {
            const int cb = kk * 32 + (lane >> 4) * 16;
            #pragma unroll
            for (int np = 0; np < 2; np++) {
                const int nb0 = np * 2, nb1 = np * 2 + 1;
                const int r0 = nb0 * 16 + (lane & 7) + ((lane >> 3) & 1) * 8;
                const int r1 = nb1 * 16 + (lane & 7) + ((lane >> 3) & 1) * 8;
                uint32_t kh0[4], kl0[4], kh1[4], kl1[4];
                ldsm4(kh0, uK  + sw128(r0, cb));
                ldsm4(kl0, uKl + sw128(r0, cb));
                ldsm4(kh1, uK  + sw128(r1, cb));
                ldsm4(kl1, uKl + sw128(r1, cb));
                mma16816(s[nb0*2+0], qh[kk], kh0[0], kh0[2]);
                mma16816(s[nb0*2+1], qh[kk], kh0[1], kh0[3]);
                mma16816(s[nb1*2+0], qh[kk], kh1[0], kh1[2]);
                mma16816(s[nb1*2+1], qh[kk], kh1[1], kh1[3]);
                mma16816(s[nb0*2+0], qh[kk], kl0[0], kl0[2]);
                mma16816(s[nb0*2+1], qh[kk], kl0[1], kl0[3]);
                mma16816(s[nb1*2+0], qh[kk], kl1[0], kl1[2]);
                mma16816(s[nb1*2+1], qh[kk], kl1[1], kl1[3]);
                mma16816(s[nb0*2+0], ql[kk], kh0[0], kh0[2]);
                mma16816(s[nb0*2+1], ql[kk], kh0[1], kh0[3]);
                mma16816(s[nb1*2+0], ql[kk], kh1[0], kh1[2]);
                mma16816(s[nb1*2+1], ql[kk], kh1[1], kh1[3]);
            }
        }
        // ---- causal mask (diagonal tiles only) ----
        if (kt >= 2 * qt) {
            const int row0 = qt * 128 + wm + g;
            #pragma unroll
            for (int j = 0; j < 8; j++) {
                const int col = kt * 64 + j * 8 + tig * 2;
                if (col     > row0)     s[j][0] = -1e30f;
                if (col + 1 > row0)     s[j][1] = -1e30f;
                if (col     > row0 + 8) s[j][2] = -1e30f;
                if (col + 1 > row0 + 8) s[j][3] = -1e30f;
            }
        }
        // ---- row max (serial point) ----
        float mx0 = -1e30f, mx1 = -1e30f;
        #pragma unroll
        for (int j = 0; j < 8; j++) {
            mx0 = fmaxf(mx0, fmaxf(s[j][0], s[j][1]));
            mx1 = fmaxf(mx1, fmaxf(s[j][2], s[j][3]));
        }
        mx0 = fmaxf(mx0, __shfl_xor_sync(0xffffffffu, mx0, 1));
        mx0 = fmaxf(mx0, __shfl_xor_sync(0xffffffffu, mx0, 2));
        mx1 = fmaxf(mx1, __shfl_xor_sync(0xffffffffu, mx1, 1));
        mx1 = fmaxf(mx1, __shfl_xor_sync(0xffffffffu, mx1, 2));
        if (mx0 > m0v || mx1 > m1v) {        // max moved: rescale l and O
            const float mn0 = fmaxf(m0v, mx0), mn1 = fmaxf(m1v, mx1);
            const float cor0 = ex2(m0v - mn0), cor1 = ex2(m1v - mn1);
            l0 *= cor0; l1 *= cor1;
            m0v = mn0; m1v = mn1;
            #pragma unroll
            for (int j = 0; j < 8; j++) {
                o[j][0] *= cor0; o[j][1] *= cor0;
                o[j][2] *= cor1; o[j][3] *= cor1;
            }
        }
        // ---- fused exp + pack + PV (per-kk interleave: MUFU/FMA overlap MMA)
        float ls0 = 0.f, ls1 = 0.f;
        #pragma unroll
        for (int kk = 0; kk < 4; kk++) {
            const int r = kk * 16 + (lane & 7) + ((lane >> 4) << 3);
            const int cb0 = 0  + ((lane >> 3) & 1) * 16;
            const int cb1 = 32 + ((lane >> 3) & 1) * 16;
            const int cb2 = 64 + ((lane >> 3) & 1) * 16;
            const int cb3 = 96 + ((lane >> 3) & 1) * 16;
            uint32_t vh0[4], vl0[4], vh1[4], vl1[4];
            ldsm4t(vh0, uV  + sw128(r, cb0));
            ldsm4t(vl0, uVl + sw128(r, cb0));
            ldsm4t(vh1, uV  + sw128(r, cb1));
            ldsm4t(vl1, uVl + sw128(r, cb1));

            float p0 = ex2(s[2*kk  ][0] - m0v), p1 = ex2(s[2*kk  ][1] - m0v);
            float p2 = ex2(s[2*kk  ][2] - m1v), p3 = ex2(s[2*kk  ][3] - m1v);
            float p4 = ex2(s[2*kk+1][0] - m0v), p5 = ex2(s[2*kk+1][1] - m0v);
            float p6 = ex2(s[2*kk+1][2] - m1v), p7 = ex2(s[2*kk+1][3] - m1v);
            ls0 += (p0 + p1) + (p4 + p5);
            ls1 += (p2 + p3) + (p6 + p7);
            uint32_t pah[4], pal[4];
            pack_split(p0, p1, pah[0], pal[0]);
            pack_split(p2, p3, pah[1], pal[1]);
            pack_split(p4, p5, pah[2], pal[2]);
            pack_split(p6, p7, pah[3], pal[3]);

            mma16816(o[0], pah, vh0[0], vh0[2]);
            mma16816(o[1], pah, vh0[1], vh0[3]);
            mma16816(o[2], pah, vh1[0], vh1[2]);
            mma16816(o[3], pah, vh1[1], vh1[3]);
            mma16816(o[0], pah, vl0[0], vl0[2]);
            mma16816(o[1], pah, vl0[1], vl0[3]);
            mma16816(o[2], pah, vl1[0], vl1[2]);
            mma16816(o[3], pah, vl1[1], vl1[3]);
            mma16816(o[0], pal, vh0[0], vh0[2]);
            mma16816(o[1], pal, vh0[1], vh0[3]);
            mma16816(o[2], pal, vh1[0], vh1[2]);
            mma16816(o[3], pal, vh1[1], vh1[3]);

            uint32_t wh0[4], wl0[4], wh1[4], wl1[4];
            ldsm4t(wh0, uV  + sw128(r, cb2));
            ldsm4t(wl0, uVl + sw128(r, cb2));
            ldsm4t(wh1, uV  + sw128(r, cb3));
            ldsm4t(wl1, uVl + sw128(r, cb3));
            mma16816(o[4], pah, wh0[0], wh0[2]);
            mma16816(o[5], pah, wh0[1], wh0[3]);
            mma16816(o[6], pah, wh1[0], wh1[2]);
            mma16816(o[7], pah, wh1[1], wh1[3]);
            mma16816(o[4], pah, wl0[0], wl0[2]);
            mma16816(o[5], pah, wl0[1], wl0[3]);
            mma16816(o[6], pah, wl1[0], wl1[2]);
            mma16816(o[7], pah, wl1[1], wl1[3]);
            mma16816(o[4], pal, wh0[0], wh0[2]);
            mma16816(o[5], pal, wh0[1], wh0[3]);
            mma16816(o[6], pal, wh1[0], wh1[2]);
            mma16816(o[7], pal, wh1[1], wh1[3]);
        }
        ls0 += __shfl_xor_sync(0xffffffffu, ls0, 1);
        ls0 += __shfl_xor_sync(0xffffffffu, ls0, 2);
        ls1 += __shfl_xor_sync(0xffffffffu, ls1, 1);
        ls1 += __shfl_xor_sync(0xffffffffu, ls1, 2);
        l0 += ls0;
        l1 += ls1;

        stc = (stc == 2) ? 0 : stc + 1;
        stp = (stp == 2) ? 0 : stp + 1;
    }

    // ---- epilogue ----
    const float inv0 = 1.0f / (l0 + 1e-10f);
    const float inv1 = 1.0f / (l1 + 1e-10f);
    const int row0 = qt * 128 + wm + g;
    #pragma unroll
    for (int j = 0; j < 8; j++) {
        const int col = h * DH + j * 8 + tig * 2;
        {
            const size_t off = (size_t)(b * NSEQ + row0) * AO_N + col;
            uint32_t ph, pl;
            pack_split(o[j][0] * inv0, o[j][1] * inv0, ph, pl);
            *(uint32_t*)(g_ao_hi + off) = ph;
            *(uint32_t*)(g_ao_lo + off) = pl;
        }
        {
            const size_t off = (size_t)(b * NSEQ + row0 + 8) * AO_N + col;
            uint32_t ph, pl;
            pack_split(o[j][2] * inv1, o[j][3] * inv1, ph, pl);
            *(uint32_t*)(g_ao_hi + off) = ph;
            *(uint32_t*)(g_ao_lo + off) = pl;
        }
    }
}

// ===================== launch ================================================
extern "C" void kernel_launch(void* const* d_in, const int* in_sizes, int n_in,
                              void* d_out, int out_size) {
    const float* x     = (const float*)d_in[0];
    const float* gamma = (const float*)d_in[1];
    const float* beta  = (const float*)d_in[2];
    const float* wqkv  = (const float*)d_in[3];
    const float* wout  = (const float*)d_in[4];
    float* out = (float*)d_out;

    cudaFuncSetAttribute(gemm_mma<0>, cudaFuncAttributeMaxDynamicSharedMemorySize, 3 * GSTAGE);
    cudaFuncSetAttribute(gemm_mma<1>, cudaFuncAttributeMaxDynamicSharedMemorySize, 3 * GSTAGE);
    cudaFuncSetAttribute(attn_kernel, cudaFuncAttributeMaxDynamicSharedMemorySize, 3 * AST);

    prep_kernel<<<TOKENS + CONV0_BLKS + CONV1_BLKS, 256>>>(x, gamma, beta, wqkv, wout);
    gemm_mma<0><<<dim3(QKV_N / 128, TOKENS / 128), 256, 3 * GSTAGE>>>(nullptr);
    attn_kernel<<<dim3(NSEQ / 128, BH_N), 256, 3 * AST>>>();
    gemm_mma<1><<<dim3(DIM / 128, TOKENS / 128), 256, 3 * GSTAGE>>>(out);
}

// round 9
// speedup vs baseline: 1.0020x; 1.0020x over previous
#include <cuda_runtime.h>
#include <cuda_bf16.h>
#include <stdint.h>

#define DIM     1024
#define HEADS   8
#define DH      64
#define NSEQ    4096
#define BATCH   2
#define TOKENS  (BATCH*NSEQ)     // 8192
#define QKV_N   (3*HEADS*DH)     // 1536
#define AO_N    (HEADS*DH)       // 512
#define BH_N    (BATCH*HEADS)    // 16
#define QSCALE  0.18033688011112042f   // 0.125 * log2(e)

// ===================== scratch globals =======================================
__device__ __align__(16) __nv_bfloat16 g_xn_hi[TOKENS * DIM];
__device__ __align__(16) __nv_bfloat16 g_xn_lo[TOKENS * DIM];
__device__ __align__(16) __nv_bfloat16 g_wq_hi[QKV_N * DIM];
__device__ __align__(16) __nv_bfloat16 g_wq_lo[QKV_N * DIM];
__device__ __align__(16) __nv_bfloat16 g_wo_hi[DIM * AO_N];
__device__ __align__(16) __nv_bfloat16 g_wo_lo[DIM * AO_N];
__device__ __align__(16) __nv_bfloat16 g_qh[BH_N * NSEQ * DH]; // log2-scaled
__device__ __align__(16) __nv_bfloat16 g_ql[BH_N * NSEQ * DH];
__device__ __align__(16) __nv_bfloat16 g_kh[BH_N * NSEQ * DH];
__device__ __align__(16) __nv_bfloat16 g_kl[BH_N * NSEQ * DH];
__device__ __align__(16) __nv_bfloat16 g_vh[BH_N * NSEQ * DH];
__device__ __align__(16) __nv_bfloat16 g_vl[BH_N * NSEQ * DH];
__device__ __align__(16) __nv_bfloat16 g_ao_hi[TOKENS * AO_N];
__device__ __align__(16) __nv_bfloat16 g_ao_lo[TOKENS * AO_N];

// ===================== PTX helpers ===========================================
__device__ __forceinline__ uint32_t smem_u32(const void* p) {
    uint32_t a;
    asm("{ .reg .u64 t; cvta.to.shared.u64 t, %1; cvt.u32.u64 %0, t; }"
        : "=r"(a) : "l"(p));
    return a;
}
__device__ __forceinline__ void cp16(uint32_t dst, const void* src) {
    asm volatile("cp.async.cg.shared.global [%0], [%1], 16;"
                 :: "r"(dst), "l"(src));
}
#define CP_COMMIT() asm volatile("cp.async.commit_group;" ::: "memory")
#define CP_WAIT1()  asm volatile("cp.async.wait_group 1;"  ::: "memory")

__device__ __forceinline__ void ldsm4(uint32_t (&r)[4], uint32_t a) {
    asm volatile("ldmatrix.sync.aligned.m8n8.x4.shared.b16 {%0,%1,%2,%3}, [%4];"
        : "=r"(r[0]), "=r"(r[1]), "=r"(r[2]), "=r"(r[3]) : "r"(a));
}
__device__ __forceinline__ void ldsm4t(uint32_t (&r)[4], uint32_t a) {
    asm volatile("ldmatrix.sync.aligned.m8n8.x4.trans.shared.b16 {%0,%1,%2,%3}, [%4];"
        : "=r"(r[0]), "=r"(r[1]), "=r"(r[2]), "=r"(r[3]) : "r"(a));
}
__device__ __forceinline__ void mma16816(float (&d)[4], const uint32_t (&a)[4],
                                         uint32_t b0, uint32_t b1) {
    asm volatile(
        "mma.sync.aligned.m16n8k16.row.col.f32.bf16.bf16.f32 "
        "{%0,%1,%2,%3}, {%4,%5,%6,%7}, {%8,%9}, {%0,%1,%2,%3};"
        : "+f"(d[0]), "+f"(d[1]), "+f"(d[2]), "+f"(d[3])
        : "r"(a[0]), "r"(a[1]), "r"(a[2]), "r"(a[3]), "r"(b0), "r"(b1));
}
__device__ __forceinline__ float ex2(float x) {
    float y;
    asm("ex2.approx.f32 %0, %1;" : "=f"(y) : "f"(x));
    return y;
}
__device__ __forceinline__ void pack_split(float x0, float x1,
                                           uint32_t& ph, uint32_t& pl) {
    uint32_t hp;
    asm("cvt.rn.bf16x2.f32 %0, %1, %2;" : "=r"(hp) : "f"(x1), "f"(x0));
    __nv_bfloat162 hv = *reinterpret_cast<__nv_bfloat162*>(&hp);
    float r0 = x0 - __bfloat162float(hv.x);
    float r1 = x1 - __bfloat162float(hv.y);
    asm("cvt.rn.bf16x2.f32 %0, %1, %2;" : "=r"(pl) : "f"(r1), "f"(r0));
    ph = hp;
}
__device__ __forceinline__ uint32_t sw128(int r, int cb) {
    return (uint32_t)(r * 128 + ((((cb >> 4) ^ (r & 7))) << 4));
}

// ===================== 1) fused prep: LN + both weight converts ==============
#define CONV0_BLKS ((QKV_N / 32) * (DIM / 32))   // 1536
#define CONV1_BLKS ((DIM / 32) * (AO_N / 32))    // 512
__global__ void prep_kernel(const float* __restrict__ x,
                            const float* __restrict__ gamma,
                            const float* __restrict__ beta,
                            const float* __restrict__ wqkv,
                            const float* __restrict__ wout) {
    const int blk = blockIdx.x;
    const int tid = threadIdx.x;
    if (blk < TOKENS) {
        const int t = blk;
        const float4 v = *(const float4*)(x + (size_t)t * DIM + tid * 4);
        float s  = v.x + v.y + v.z + v.w;
        float s2 = v.x*v.x + v.y*v.y + v.z*v.z + v.w*v.w;
        #pragma unroll
        for (int o = 16; o > 0; o >>= 1) {
            s  += __shfl_down_sync(0xffffffffu, s,  o);
            s2 += __shfl_down_sync(0xffffffffu, s2, o);
        }
        __shared__ float ws[8], ws2[8];
        __shared__ float s_mu, s_rstd;
        const int wid = tid >> 5, lane = tid & 31;
        if (lane == 0) { ws[wid] = s; ws2[wid] = s2; }
        __syncthreads();
        if (tid == 0) {
            float S = 0.f, S2 = 0.f;
            #pragma unroll
            for (int i = 0; i < 8; i++) { S += ws[i]; S2 += ws2[i]; }
            float mu  = S * (1.0f / DIM);
            float var = S2 * (1.0f / DIM) - mu * mu;
            s_mu = mu;
            s_rstd = rsqrtf(var + 1e-5f);
        }
        __syncthreads();
        const float mu = s_mu, rstd = s_rstd;
        const float4 g = *(const float4*)(gamma + tid * 4);
        const float4 b = *(const float4*)(beta  + tid * 4);
        float y[4];
        y[0] = (v.x - mu) * rstd * g.x + b.x;
        y[1] = (v.y - mu) * rstd * g.y + b.y;
        y[2] = (v.z - mu) * rstd * g.z + b.z;
        y[3] = (v.w - mu) * rstd * g.w + b.w;
        const size_t o = (size_t)t * DIM + tid * 4;
        uint32_t h0, l0, h1, l1;
        pack_split(y[0], y[1], h0, l0);
        pack_split(y[2], y[3], h1, l1);
        *(uint32_t*)(g_xn_hi + o)     = h0;
        *(uint32_t*)(g_xn_hi + o + 2) = h1;
        *(uint32_t*)(g_xn_lo + o)     = l0;
        *(uint32_t*)(g_xn_lo + o + 2) = l1;
    } else {
        __shared__ float tbuf[32][33];
        int idx, Kd, Nd;
        const float* src;
        __nv_bfloat16 *hi, *lo;
        if (blk < TOKENS + CONV0_BLKS) {
            idx = blk - TOKENS; Kd = DIM; Nd = QKV_N;
            src = wqkv; hi = g_wq_hi; lo = g_wq_lo;
        } else {
            idx = blk - TOKENS - CONV0_BLKS; Kd = AO_N; Nd = DIM;
            src = wout; hi = g_wo_hi; lo = g_wo_lo;
        }
        const int nb = Nd / 32;
        const int n0 = (idx % nb) * 32, k0 = (idx / nb) * 32;
        const int tx = tid & 31, ty = tid >> 5;
        #pragma unroll
        for (int i = ty; i < 32; i += 8)
            tbuf[i][tx] = src[(size_t)(k0 + i) * Nd + n0 + tx];
        __syncthreads();
        #pragma unroll
        for (int i = ty; i < 32; i += 8) {
            const float v = tbuf[tx][i];
            const __nv_bfloat16 h = __float2bfloat16(v);
            const size_t off = (size_t)(n0 + i) * Kd + k0 + tx;
            hi[off] = h;
            lo[off] = __float2bfloat16(v - __bfloat162float(h));
        }
    }
}

// ===================== 2) GEMM: 128x128 tile, 4 warps (64x64/warp), 3-stage ==
// stage (32768 B): A 128 rows x [32 hi | 32 lo] cols (128B swizzled rows),
//                  B same at +16384.
#define GSTAGE 32768
__device__ __forceinline__ void gemm_load3(uint32_t sb, int st,
    const __nv_bfloat16* __restrict__ Ah, const __nv_bfloat16* __restrict__ Al,
    const __nv_bfloat16* __restrict__ Bh, const __nv_bfloat16* __restrict__ Bl,
    int m0, int n0, int K, int k0, int tid)
{
    const uint32_t base = sb + st * GSTAGE;
    #pragma unroll
    for (int t = 0; t < 16; t++) {
        const int rc = tid + (t & 7) * 128;     // 0..1023
        const int r = rc >> 3, c = rc & 7;
        const int isB = t >> 3;
        const uint32_t d = base + isB * 16384 + sw128(r, c * 16);
        const int row = (isB ? n0 : m0) + r;
        const __nv_bfloat16* hi = isB ? Bh : Ah;
        const __nv_bfloat16* lo = isB ? Bl : Al;
        const __nv_bfloat16* src = (c < 4)
            ? (hi + (size_t)row * K + k0 + c * 8)
            : (lo + (size_t)row * K + k0 + (c - 4) * 8);
        cp16(d, src);
    }
}

template<int MODE>
__global__ void __launch_bounds__(128, 2) gemm_mma(float* __restrict__ Cout) {
    constexpr int K  = (MODE == 0) ? DIM : AO_N;
    constexpr int NC = K / 32;
    extern __shared__ char dsm[];
    const uint32_t sb = smem_u32(dsm);

    const int tid = threadIdx.x, lane = tid & 31, warp = tid >> 5;
    const int g = lane >> 2, tig = lane & 3;
    const int wm = (warp >> 1) * 64, wn = (warp & 1) * 64;
    const int m0 = blockIdx.y * 128, n0 = blockIdx.x * 128;

    const __nv_bfloat16* __restrict__ Ah = (MODE == 0) ? g_xn_hi : g_ao_hi;
    const __nv_bfloat16* __restrict__ Al = (MODE == 0) ? g_xn_lo : g_ao_lo;
    const __nv_bfloat16* __restrict__ Bh = (MODE == 0) ? g_wq_hi : g_wo_hi;
    const __nv_bfloat16* __restrict__ Bl = (MODE == 0) ? g_wq_lo : g_wo_lo;

    float c[4][8][4] = {};

    gemm_load3(sb, 0, Ah, Al, Bh, Bl, m0, n0, K, 0,  tid);
    CP_COMMIT();
    gemm_load3(sb, 1, Ah, Al, Bh, Bl, m0, n0, K, 32, tid);
    CP_COMMIT();

    int stc = 0, stp = 2;
    for (int cc = 0; cc < NC; cc++) {
        CP_WAIT1();
        __syncthreads();
        if (cc + 2 < NC)
            gemm_load3(sb, stp, Ah, Al, Bh, Bl, m0, n0, K, (cc + 2) * 32, tid);
        CP_COMMIT();

        const uint32_t uA = sb + stc * GSTAGE;
        const uint32_t uB = uA + 16384;

        #pragma unroll
        for (int hh = 0; hh < 2; hh++) {
            const int acb = hh * 32 + (lane >> 4) * 16;
            uint32_t ah[4][4], al[4][4];
            #pragma unroll
            for (int i = 0; i < 4; i++) {
                const int row = wm + i * 16 + (lane & 15);
                ldsm4(ah[i], uA + sw128(row, acb));
                ldsm4(al[i], uA + sw128(row, acb + 64));
            }
            #pragma unroll
            for (int nb = 0; nb < 4; nb++) {
                const int row = wn + nb * 16 + (lane & 7) + ((lane >> 3) & 1) * 8;
                uint32_t bhh[4], bll[4];
                ldsm4(bhh, uB + sw128(row, acb));
                ldsm4(bll, uB + sw128(row, acb + 64));
                #pragma unroll
                for (int i = 0; i < 4; i++) {
                    mma16816(c[i][nb*2+0], ah[i], bhh[0], bhh[2]);
                    mma16816(c[i][nb*2+1], ah[i], bhh[1], bhh[3]);
                    mma16816(c[i][nb*2+0], ah[i], bll[0], bll[2]);
                    mma16816(c[i][nb*2+1], ah[i], bll[1], bll[3]);
                    mma16816(c[i][nb*2+0], al[i], bhh[0], bhh[2]);
                    mma16816(c[i][nb*2+1], al[i], bhh[1], bhh[3]);
                }
            }
        }
        stc = (stc == 2) ? 0 : stc + 1;
        stp = (stp == 2) ? 0 : stp + 1;
    }

    if (MODE == 0) {
        #pragma unroll
        for (int i = 0; i < 4; i++) {
            const int r0g = m0 + wm + i * 16 + g;
            #pragma unroll
            for (int j = 0; j < 8; j++) {
                const int col  = n0 + wn + j * 8 + tig * 2;
                const int part = col >> 9;
                const int hd   = (col >> 6) & 7;
                const int d    = col & 63;
                __nv_bfloat16* dh_ = (part == 0) ? g_qh : ((part == 1) ? g_kh : g_vh);
                __nv_bfloat16* dl_ = (part == 0) ? g_ql : ((part == 1) ? g_kl : g_vl);
                const float sc = (part == 0) ? QSCALE : 1.0f;
                #pragma unroll
                for (int rr = 0; rr < 2; rr++) {
                    const int row = r0g + rr * 8;
                    const int bb = row >> 12, seq = row & 4095;
                    const size_t off = (((size_t)(bb * HEADS + hd)) * NSEQ + seq) * DH + d;
                    uint32_t ph, pl;
                    pack_split(c[i][j][rr*2+0] * sc, c[i][j][rr*2+1] * sc, ph, pl);
                    *(uint32_t*)(dh_ + off) = ph;
                    *(uint32_t*)(dl_ + off) = pl;
                }
            }
        }
    } else {
        #pragma unroll
        for (int i = 0; i < 4; i++) {
            const int r0g = m0 + wm + i * 16 + g;
            #pragma unroll
            for (int j = 0; j < 8; j++) {
                const int col = n0 + wn + j * 8 + tig * 2;
                #pragma unroll
                for (int rr = 0; rr < 2; rr++) {
                    const int row = r0g + rr * 8;
                    *(float2*)(Cout + (size_t)row * DIM + col) =
                        make_float2(c[i][j][rr*2+0], c[i][j][rr*2+1]);
                }
            }
        }
    }
}

// ===================== 3) flash attention: Br=128, 4 warps (32 rows/warp) ====
// stage (32768 B): KH@0, KL@8192, VH@16384, VL@24576 — 64 rows x 128B swizzled
#define AST 32768
__device__ __forceinline__ void kv_load(uint32_t sb, int st, size_t kvbase,
                                        int kt, int tid) {
    const int r  = tid >> 1;                // 0..63
    const int c0 = (tid & 1) * 4;           // 0 or 4
    const uint32_t base = sb + st * AST;
    #pragma unroll
    for (int it = 0; it < 4; it++) {
        const int ch = c0 + it;
        const uint32_t d = base + sw128(r, ch * 16);
        const size_t src = kvbase + (size_t)(kt * 64 + r) * DH + ch * 8;
        cp16(d,         g_kh + src);
        cp16(d + 8192,  g_kl + src);
        cp16(d + 16384, g_vh + src);
        cp16(d + 24576, g_vl + src);
    }
}

__global__ void __launch_bounds__(128, 2) attn_kernel() {
    extern __shared__ char dsm[];
    const uint32_t sb = smem_u32(dsm);
    const int qt = (int)gridDim.x - 1 - (int)blockIdx.x;  // big tiles first
    const int bh = blockIdx.y, b = bh >> 3, h = bh & 7;
    const int tid = threadIdx.x, lane = tid & 31, warp = tid >> 5;
    const int g = lane >> 2, tig = lane & 3;
    const int wm = warp * 32;
    const size_t kvbase = (size_t)bh * NSEQ * DH;

    // ---- stage Q into stage-1/2 areas (QH @32768, QL @65536) ----
    const size_t qbase = ((size_t)bh * NSEQ + qt * 128) * DH;
    for (int i = tid; i < 1024; i += 128) {
        const int r = i >> 3, cch = i & 7;
        const uint32_t d = sw128(r, cch * 16);
        const size_t src = qbase + (size_t)r * DH + cch * 8;
        *(uint4*)(dsm + 32768 + d) = *(const uint4*)(g_qh + src);
        *(uint4*)(dsm + 65536 + d) = *(const uint4*)(g_ql + src);
    }
    __syncthreads();
    uint32_t qh[2][4][4], ql[2][4][4];      // [mfrag][kk]
    #pragma unroll
    for (int mf = 0; mf < 2; mf++)
        #pragma unroll
        for (int kk = 0; kk < 4; kk++) {
            const int r  = wm + mf * 16 + (lane & 15);
            const int cb = kk * 32 + (lane >> 4) * 16;
            const uint32_t off = sw128(r, cb);
            ldsm4(qh[mf][kk], sb + 32768 + off);
            ldsm4(ql[mf][kk], sb + 65536 + off);
        }
    __syncthreads();                         // Q area free for KV stages

    const int ktmax = 2 * qt + 1;
    kv_load(sb, 0, kvbase, 0, tid);
    CP_COMMIT();
    kv_load(sb, 1, kvbase, 1, tid);
    CP_COMMIT();

    float o[2][8][4] = {};
    float mv[4] = {-1e30f, -1e30f, -1e30f, -1e30f};
    float lv[4] = {0.f, 0.f, 0.f, 0.f};

    int stc = 0, stp = 2;
    for (int kt = 0; kt <= ktmax; kt++) {
        CP_WAIT1();
        __syncthreads();
        if (kt + 2 <= ktmax)
            kv_load(sb, stp, kvbase, kt + 2, tid);
        CP_COMMIT();

        const uint32_t uK  = sb + stc * AST;
        const uint32_t uKl = uK + 8192;
        const uint32_t uV  = uK + 16384;
        const uint32_t uVl = uK + 24576;

        // ---- S = Q K^T (3-term bf16), log2 domain ----
        float s[2][8][4] = {};
        #pragma unroll
        for (int kk = 0; kk < 4; kk++) {
            const int cb = kk * 32 + (lane >> 4) * 16;
            #pragma unroll
            for (int np = 0; np < 2; np++) {
                const int nb0 = np * 2, nb1 = np * 2 + 1;
                const int r0 = nb0 * 16 + (lane & 7) + ((lane >> 3) & 1) * 8;
                const int r1 = nb1 * 16 + (lane & 7) + ((lane >> 3) & 1) * 8;
                uint32_t kh0[4], kl0[4], kh1[4], kl1[4];
                ldsm4(kh0, uK  + sw128(r0, cb));
                ldsm4(kl0, uKl + sw128(r0, cb));
                ldsm4(kh1, uK  + sw128(r1, cb));
                ldsm4(kl1, uKl + sw128(r1, cb));
                #pragma unroll
                for (int mf = 0; mf < 2; mf++) {
                    mma16816(s[mf][nb0*2+0], qh[mf][kk], kh0[0], kh0[2]);
                    mma16816(s[mf][nb0*2+1], qh[mf][kk], kh0[1], kh0[3]);
                    mma16816(s[mf][nb1*2+0], qh[mf][kk], kh1[0], kh1[2]);
                    mma16816(s[mf][nb1*2+1], qh[mf][kk], kh1[1], kh1[3]);
                    mma16816(s[mf][nb0*2+0], qh[mf][kk], kl0[0], kl0[2]);
                    mma16816(s[mf][nb0*2+1], qh[mf][kk], kl0[1], kl0[3]);
                    mma16816(s[mf][nb1*2+0], qh[mf][kk], kl1[0], kl1[2]);
                    mma16816(s[mf][nb1*2+1], qh[mf][kk], kl1[1], kl1[3]);
                    mma16816(s[mf][nb0*2+0], ql[mf][kk], kh0[0], kh0[2]);
                    mma16816(s[mf][nb0*2+1], ql[mf][kk], kh0[1], kh0[3]);
                    mma16816(s[mf][nb1*2+0], ql[mf][kk], kh1[0], kh1[2]);
                    mma16816(s[mf][nb1*2+1], ql[mf][kk], kh1[1], kh1[3]);
                }
            }
        }
        // ---- causal mask (diagonal tiles only) ----
        if (kt >= 2 * qt) {
            #pragma unroll
            for (int mf = 0; mf < 2; mf++) {
                const int row0 = qt * 128 + wm + mf * 16 + g;
                #pragma unroll
                for (int j = 0; j < 8; j++) {
                    const int col = kt * 64 + j * 8 + tig * 2;
                    if (col     > row0)     s[mf][j][0] = -1e30f;
                    if (col + 1 > row0)     s[mf][j][1] = -1e30f;
                    if (col     > row0 + 8) s[mf][j][2] = -1e30f;
                    if (col + 1 > row0 + 8) s[mf][j][3] = -1e30f;
                }
            }
        }
        // ---- row max ----
        float mx[4] = {-1e30f, -1e30f, -1e30f, -1e30f};
        #pragma unroll
        for (int mf = 0; mf < 2; mf++)
            #pragma unroll
            for (int j = 0; j < 8; j++) {
                mx[mf*2+0] = fmaxf(mx[mf*2+0], fmaxf(s[mf][j][0], s[mf][j][1]));
                mx[mf*2+1] = fmaxf(mx[mf*2+1], fmaxf(s[mf][j][2], s[mf][j][3]));
            }
        #pragma unroll
        for (int i = 0; i < 4; i++) {
            mx[i] = fmaxf(mx[i], __shfl_xor_sync(0xffffffffu, mx[i], 1));
            mx[i] = fmaxf(mx[i], __shfl_xor_sync(0xffffffffu, mx[i], 2));
        }
        if (mx[0] > mv[0] || mx[1] > mv[1] || mx[2] > mv[2] || mx[3] > mv[3]) {
            float cor[4];
            #pragma unroll
            for (int i = 0; i < 4; i++) {
                const float mn = fmaxf(mv[i], mx[i]);
                cor[i] = ex2(mv[i] - mn);
                lv[i] *= cor[i];
                mv[i] = mn;
            }
            #pragma unroll
            for (int mf = 0; mf < 2; mf++)
                #pragma unroll
                for (int j = 0; j < 8; j++) {
                    o[mf][j][0] *= cor[mf*2+0]; o[mf][j][1] *= cor[mf*2+0];
                    o[mf][j][2] *= cor[mf*2+1]; o[mf][j][3] *= cor[mf*2+1];
                }
        }
        // ---- exp + pack + PV ----
        float ls[4] = {0.f, 0.f, 0.f, 0.f};
        #pragma unroll
        for (int kk = 0; kk < 4; kk++) {
            const int r = kk * 16 + (lane & 7) + ((lane >> 4) << 3);
            uint32_t pah[2][4], pal[2][4];
            #pragma unroll
            for (int mf = 0; mf < 2; mf++) {
                float p0 = ex2(s[mf][2*kk  ][0] - mv[mf*2+0]);
                float p1 = ex2(s[mf][2*kk  ][1] - mv[mf*2+0]);
                float p2 = ex2(s[mf][2*kk  ][2] - mv[mf*2+1]);
                float p3 = ex2(s[mf][2*kk  ][3] - mv[mf*2+1]);
                float p4 = ex2(s[mf][2*kk+1][0] - mv[mf*2+0]);
                float p5 = ex2(s[mf][2*kk+1][1] - mv[mf*2+0]);
                float p6 = ex2(s[mf][2*kk+1][2] - mv[mf*2+1]);
                float p7 = ex2(s[mf][2*kk+1][3] - mv[mf*2+1]);
                ls[mf*2+0] += (p0 + p1) + (p4 + p5);
                ls[mf*2+1] += (p2 + p3) + (p6 + p7);
                pack_split(p0, p1, pah[mf][0], pal[mf][0]);
                pack_split(p2, p3, pah[mf][1], pal[mf][1]);
                pack_split(p4, p5, pah[mf][2], pal[mf][2]);
                pack_split(p6, p7, pah[mf][3], pal[mf][3]);
            }
            #pragma unroll
            for (int half = 0; half < 2; half++) {
                uint32_t vh0[4], vl0[4], vh1[4], vl1[4];
                const int nb0 = half * 2, nb1 = half * 2 + 1;
                const int cb0 = nb0 * 32 + ((lane >> 3) & 1) * 16;
                const int cb1 = nb1 * 32 + ((lane >> 3) & 1) * 16;
                ldsm4t(vh0, uV  + sw128(r, cb0));
                ldsm4t(vl0, uVl + sw128(r, cb0));
                ldsm4t(vh1, uV  + sw128(r, cb1));
                ldsm4t(vl1, uVl + sw128(r, cb1));
                #pragma unroll
                for (int mf = 0; mf < 2; mf++) {
                    mma16816(o[mf][nb0*2+0], pah[mf], vh0[0], vh0[2]);
                    mma16816(o[mf][nb0*2+1], pah[mf], vh0[1], vh0[3]);
                    mma16816(o[mf][nb1*2+0], pah[mf], vh1[0], vh1[2]);
                    mma16816(o[mf][nb1*2+1], pah[mf], vh1[1], vh1[3]);
                    mma16816(o[mf][nb0*2+0], pah[mf], vl0[0], vl0[2]);
                    mma16816(o[mf][nb0*2+1], pah[mf], vl0[1], vl0[3]);
                    mma16816(o[mf][nb1*2+0], pah[mf], vl1[0], vl1[2]);
                    mma16816(o[mf][nb1*2+1], pah[mf], vl1[1], vl1[3]);
                    mma16816(o[mf][nb0*2+0], pal[mf], vh0[0], vh0[2]);
                    mma16816(o[mf][nb0*2+1], pal[mf], vh0[1], vh0[3]);
                    mma16816(o[mf][nb1*2+0], pal[mf], vh1[0], vh1[2]);
                    mma16816(o[mf][nb1*2+1], pal[mf], vh1[1], vh1[3]);
                }
            }
        }
        #pragma unroll
        for (int i = 0; i < 4; i++) {
            ls[i] += __shfl_xor_sync(0xffffffffu, ls[i], 1);
            ls[i] += __shfl_xor_sync(0xffffffffu, ls[i], 2);
            lv[i] += ls[i];
        }

        stc = (stc == 2) ? 0 : stc + 1;
        stp = (stp == 2) ? 0 : stp + 1;
    }

    // ---- epilogue ----
    float inv[4];
    #pragma unroll
    for (int i = 0; i < 4; i++) inv[i] = 1.0f / (lv[i] + 1e-10f);
    #pragma unroll
    for (int mf = 0; mf < 2; mf++) {
        const int row0 = qt * 128 + wm + mf * 16 + g;
        #pragma unroll
        for (int j = 0; j < 8; j++) {
            const int col = h * DH + j * 8 + tig * 2;
            {
                const size_t off = (size_t)(b * NSEQ + row0) * AO_N + col;
                uint32_t ph, pl;
                pack_split(o[mf][j][0] * inv[mf*2+0], o[mf][j][1] * inv[mf*2+0], ph, pl);
                *(uint32_t*)(g_ao_hi + off) = ph;
                *(uint32_t*)(g_ao_lo + off) = pl;
            }
            {
                const size_t off = (size_t)(b * NSEQ + row0 + 8) * AO_N + col;
                uint32_t ph, pl;
                pack_split(o[mf][j][2] * inv[mf*2+1], o[mf][j][3] * inv[mf*2+1], ph, pl);
                *(uint32_t*)(g_ao_hi + off) = ph;
                *(uint32_t*)(g_ao_lo + off) = pl;
            }
        }
    }
}

// ===================== launch ================================================
extern "C" void kernel_launch(void* const* d_in, const int* in_sizes, int n_in,
                              void* d_out, int out_size) {
    const float* x     = (const float*)d_in[0];
    const float* gamma = (const float*)d_in[1];
    const float* beta  = (const float*)d_in[2];
    const float* wqkv  = (const float*)d_in[3];
    const float* wout  = (const float*)d_in[4];
    float* out = (float*)d_out;

    cudaFuncSetAttribute(gemm_mma<0>, cudaFuncAttributeMaxDynamicSharedMemorySize, 3 * GSTAGE);
    cudaFuncSetAttribute(gemm_mma<1>, cudaFuncAttributeMaxDynamicSharedMemorySize, 3 * GSTAGE);
    cudaFuncSetAttribute(attn_kernel, cudaFuncAttributeMaxDynamicSharedMemorySize, 3 * AST);

    prep_kernel<<<TOKENS + CONV0_BLKS + CONV1_BLKS, 256>>>(x, gamma, beta, wqkv, wout);
    gemm_mma<0><<<dim3(QKV_N / 128, TOKENS / 128), 128, 3 * GSTAGE>>>(nullptr);
    attn_kernel<<<dim3(NSEQ / 128, BH_N), 128, 3 * AST>>>();
    gemm_mma<1><<<dim3(DIM / 128, TOKENS / 128), 128, 3 * GSTAGE>>>(out);
}

// round 10
// speedup vs baseline: 1.3035x; 1.3009x over previous
#include <cuda_runtime.h>
#include <cuda_fp16.h>
#include <stdint.h>

#define DIM     1024
#define HEADS   8
#define DH      64
#define NSEQ    4096
#define BATCH   2
#define TOKENS  (BATCH*NSEQ)     // 8192
#define QKV_N   (3*HEADS*DH)     // 1536
#define AO_N    (HEADS*DH)       // 512
#define BH_N    (BATCH*HEADS)    // 16
#define QSCALE  0.18033688011112042f   // 0.125 * log2(e)

// ===================== scratch globals (fp16) ================================
__device__ __align__(16) __half g_xn_hi[TOKENS * DIM];
__device__ __align__(16) __half g_wq_hi[QKV_N * DIM];
__device__ __align__(16) __half g_wq_lo[QKV_N * DIM];
__device__ __align__(16) __half g_wo_hi[DIM * AO_N];
__device__ __align__(16) __half g_wo_lo[DIM * AO_N];
__device__ __align__(16) __half g_qh[BH_N * NSEQ * DH];  // log2-scaled
__device__ __align__(16) __half g_ql[BH_N * NSEQ * DH];
__device__ __align__(16) __half g_kh[BH_N * NSEQ * DH];
__device__ __align__(16) __half g_kl[BH_N * NSEQ * DH];
__device__ __align__(16) __half g_vh[BH_N * NSEQ * DH];
__device__ __align__(16) __half g_vl[BH_N * NSEQ * DH];
__device__ __align__(16) __half g_ao_hi[TOKENS * AO_N];

// ===================== PTX helpers ===========================================
__device__ __forceinline__ uint32_t smem_u32(const void* p) {
    uint32_t a;
    asm("{ .reg .u64 t; cvta.to.shared.u64 t, %1; cvt.u32.u64 %0, t; }"
        : "=r"(a) : "l"(p));
    return a;
}
__device__ __forceinline__ void cp16(uint32_t dst, const void* src) {
    asm volatile("cp.async.cg.shared.global [%0], [%1], 16;"
                 :: "r"(dst), "l"(src));
}
#define CP_COMMIT() asm volatile("cp.async.commit_group;" ::: "memory")
#define CP_WAIT1()  asm volatile("cp.async.wait_group 1;"  ::: "memory")

__device__ __forceinline__ void ldsm4(uint32_t (&r)[4], uint32_t a) {
    asm volatile("ldmatrix.sync.aligned.m8n8.x4.shared.b16 {%0,%1,%2,%3}, [%4];"
        : "=r"(r[0]), "=r"(r[1]), "=r"(r[2]), "=r"(r[3]) : "r"(a));
}
__device__ __forceinline__ void ldsm4t(uint32_t (&r)[4], uint32_t a) {
    asm volatile("ldmatrix.sync.aligned.m8n8.x4.trans.shared.b16 {%0,%1,%2,%3}, [%4];"
        : "=r"(r[0]), "=r"(r[1]), "=r"(r[2]), "=r"(r[3]) : "r"(a));
}
__device__ __forceinline__ void mma16816(float (&d)[4], const uint32_t (&a)[4],
                                         uint32_t b0, uint32_t b1) {
    asm volatile(
        "mma.sync.aligned.m16n8k16.row.col.f32.f16.f16.f32 "
        "{%0,%1,%2,%3}, {%4,%5,%6,%7}, {%8,%9}, {%0,%1,%2,%3};"
        : "+f"(d[0]), "+f"(d[1]), "+f"(d[2]), "+f"(d[3])
        : "r"(a[0]), "r"(a[1]), "r"(a[2]), "r"(a[3]), "r"(b0), "r"(b1));
}
__device__ __forceinline__ float ex2(float x) {
    float y;
    asm("ex2.approx.f32 %0, %1;" : "=f"(y) : "f"(x));
    return y;
}
__device__ __forceinline__ void pack2h(float x0, float x1, uint32_t& ph) {
    asm("cvt.rn.f16x2.f32 %0, %1, %2;" : "=r"(ph) : "f"(x1), "f"(x0));
}
__device__ __forceinline__ void pack_split_h(float x0, float x1,
                                             uint32_t& ph, uint32_t& pl) {
    pack2h(x0, x1, ph);
    __half2 hv = *reinterpret_cast<__half2*>(&ph);
    float r0 = x0 - __half2float(hv.x);
    float r1 = x1 - __half2float(hv.y);
    pack2h(r0, r1, pl);
}
__device__ __forceinline__ uint32_t sw128(int r, int cb) {
    return (uint32_t)(r * 128 + ((((cb >> 4) ^ (r & 7))) << 4));
}

// ===================== 1) fused prep: LN (hi only) + weight converts =========
#define CONV0_BLKS ((QKV_N / 32) * (DIM / 32))   // 1536
#define CONV1_BLKS ((DIM / 32) * (AO_N / 32))    // 512
__global__ void prep_kernel(const float* __restrict__ x,
                            const float* __restrict__ gamma,
                            const float* __restrict__ beta,
                            const float* __restrict__ wqkv,
                            const float* __restrict__ wout) {
    const int blk = blockIdx.x;
    const int tid = threadIdx.x;
    if (blk < TOKENS) {
        const int t = blk;
        const float4 v = *(const float4*)(x + (size_t)t * DIM + tid * 4);
        float s  = v.x + v.y + v.z + v.w;
        float s2 = v.x*v.x + v.y*v.y + v.z*v.z + v.w*v.w;
        #pragma unroll
        for (int o = 16; o > 0; o >>= 1) {
            s  += __shfl_down_sync(0xffffffffu, s,  o);
            s2 += __shfl_down_sync(0xffffffffu, s2, o);
        }
        __shared__ float ws[8], ws2[8];
        __shared__ float s_mu, s_rstd;
        const int wid = tid >> 5, lane = tid & 31;
        if (lane == 0) { ws[wid] = s; ws2[wid] = s2; }
        __syncthreads();
        if (tid == 0) {
            float S = 0.f, S2 = 0.f;
            #pragma unroll
            for (int i = 0; i < 8; i++) { S += ws[i]; S2 += ws2[i]; }
            float mu  = S * (1.0f / DIM);
            float var = S2 * (1.0f / DIM) - mu * mu;
            s_mu = mu;
            s_rstd = rsqrtf(var + 1e-5f);
        }
        __syncthreads();
        const float mu = s_mu, rstd = s_rstd;
        const float4 g = *(const float4*)(gamma + tid * 4);
        const float4 b = *(const float4*)(beta  + tid * 4);
        float y[4];
        y[0] = (v.x - mu) * rstd * g.x + b.x;
        y[1] = (v.y - mu) * rstd * g.y + b.y;
        y[2] = (v.z - mu) * rstd * g.z + b.z;
        y[3] = (v.w - mu) * rstd * g.w + b.w;
        const size_t o = (size_t)t * DIM + tid * 4;
        uint32_t h0, h1;
        pack2h(y[0], y[1], h0);
        pack2h(y[2], y[3], h1);
        *(uint32_t*)(g_xn_hi + o)     = h0;
        *(uint32_t*)(g_xn_hi + o + 2) = h1;
    } else {
        __shared__ float tbuf[32][33];
        int idx, Kd, Nd;
        const float* src;
        __half *hi, *lo;
        if (blk < TOKENS + CONV0_BLKS) {
            idx = blk - TOKENS; Kd = DIM; Nd = QKV_N;
            src = wqkv; hi = g_wq_hi; lo = g_wq_lo;
        } else {
            idx = blk - TOKENS - CONV0_BLKS; Kd = AO_N; Nd = DIM;
            src = wout; hi = g_wo_hi; lo = g_wo_lo;
        }
        const int nb = Nd / 32;
        const int n0 = (idx % nb) * 32, k0 = (idx / nb) * 32;
        const int tx = tid & 31, ty = tid >> 5;
        #pragma unroll
        for (int i = ty; i < 32; i += 8)
            tbuf[i][tx] = src[(size_t)(k0 + i) * Nd + n0 + tx];
        __syncthreads();
        #pragma unroll
        for (int i = ty; i < 32; i += 8) {
            const float v = tbuf[tx][i];
            const __half h = __float2half_rn(v);
            const size_t off = (size_t)(n0 + i) * Kd + k0 + tx;
            hi[off] = h;
            lo[off] = __float2half_rn(v - __half2float(h));
        }
    }
}

// ===================== 2) GEMM: fp16 2-term, 128x128, 64x64/warp, 3-stage ====
// stage (32768 B): A hi 128 rows x 64B (in 128B swizzled rows), B hi|lo @+16384
#define GSTAGE 32768
__device__ __forceinline__ void gemm_load(uint32_t sb, int st,
    const __half* __restrict__ Ah,
    const __half* __restrict__ Bh, const __half* __restrict__ Bl,
    int m0, int n0, int K, int k0, int tid)
{
    const uint32_t base = sb + st * GSTAGE;
    #pragma unroll
    for (int t = 0; t < 4; t++) {               // A hi: 128 rows x 4 chunks
        const int rc = tid + t * 128;
        const int r = rc >> 2, c = rc & 3;
        cp16(base + sw128(r, c * 16), Ah + (size_t)(m0 + r) * K + k0 + c * 8);
    }
    #pragma unroll
    for (int t = 0; t < 8; t++) {               // B: hi (c<4) | lo (c>=4)
        const int rc = tid + t * 128;
        const int r = rc >> 3, c = rc & 7;
        const __half* src = (c < 4)
            ? (Bh + (size_t)(n0 + r) * K + k0 + c * 8)
            : (Bl + (size_t)(n0 + r) * K + k0 + (c - 4) * 8);
        cp16(base + 16384 + sw128(r, c * 16), src);
    }
}

template<int MODE>
__global__ void __launch_bounds__(128, 2) gemm_mma(float* __restrict__ Cout) {
    constexpr int K  = (MODE == 0) ? DIM : AO_N;
    constexpr int NC = K / 32;
    extern __shared__ char dsm[];
    const uint32_t sb = smem_u32(dsm);

    const int tid = threadIdx.x, lane = tid & 31, warp = tid >> 5;
    const int g = lane >> 2, tig = lane & 3;
    const int wm = (warp >> 1) * 64, wn = (warp & 1) * 64;
    const int m0 = blockIdx.y * 128, n0 = blockIdx.x * 128;

    const __half* __restrict__ Ah = (MODE == 0) ? g_xn_hi : g_ao_hi;
    const __half* __restrict__ Bh = (MODE == 0) ? g_wq_hi : g_wo_hi;
    const __half* __restrict__ Bl = (MODE == 0) ? g_wq_lo : g_wo_lo;

    float c[4][8][4] = {};

    gemm_load(sb, 0, Ah, Bh, Bl, m0, n0, K, 0,  tid);
    CP_COMMIT();
    gemm_load(sb, 1, Ah, Bh, Bl, m0, n0, K, 32, tid);
    CP_COMMIT();

    int stc = 0, stp = 2;
    for (int cc = 0; cc < NC; cc++) {
        CP_WAIT1();
        __syncthreads();
        if (cc + 2 < NC)
            gemm_load(sb, stp, Ah, Bh, Bl, m0, n0, K, (cc + 2) * 32, tid);
        CP_COMMIT();

        const uint32_t uA = sb + stc * GSTAGE;
        const uint32_t uB = uA + 16384;

        #pragma unroll
        for (int hh = 0; hh < 2; hh++) {
            const int acb = hh * 32 + (lane >> 4) * 16;
            uint32_t ah[4][4];
            #pragma unroll
            for (int i = 0; i < 4; i++) {
                const int row = wm + i * 16 + (lane & 15);
                ldsm4(ah[i], uA + sw128(row, acb));
            }
            #pragma unroll
            for (int nb = 0; nb < 4; nb++) {
                const int row = wn + nb * 16 + (lane & 7) + ((lane >> 3) & 1) * 8;
                uint32_t bhh[4], bll[4];
                ldsm4(bhh, uB + sw128(row, acb));
                ldsm4(bll, uB + sw128(row, acb + 64));
                #pragma unroll
                for (int i = 0; i < 4; i++) {
                    mma16816(c[i][nb*2+0], ah[i], bhh[0], bhh[2]);
                    mma16816(c[i][nb*2+1], ah[i], bhh[1], bhh[3]);
                    mma16816(c[i][nb*2+0], ah[i], bll[0], bll[2]);
                    mma16816(c[i][nb*2+1], ah[i], bll[1], bll[3]);
                }
            }
        }
        stc = (stc == 2) ? 0 : stc + 1;
        stp = (stp == 2) ? 0 : stp + 1;
    }

    if (MODE == 0) {
        #pragma unroll
        for (int i = 0; i < 4; i++) {
            const int r0g = m0 + wm + i * 16 + g;
            #pragma unroll
            for (int j = 0; j < 8; j++) {
                const int col  = n0 + wn + j * 8 + tig * 2;
                const int part = col >> 9;
                const int hd   = (col >> 6) & 7;
                const int d    = col & 63;
                __half* dh_ = (part == 0) ? g_qh : ((part == 1) ? g_kh : g_vh);
                __half* dl_ = (part == 0) ? g_ql : ((part == 1) ? g_kl : g_vl);
                const float sc = (part == 0) ? QSCALE : 1.0f;
                #pragma unroll
                for (int rr = 0; rr < 2; rr++) {
                    const int row = r0g + rr * 8;
                    const int bb = row >> 12, seq = row & 4095;
                    const size_t off = (((size_t)(bb * HEADS + hd)) * NSEQ + seq) * DH + d;
                    uint32_t ph, pl;
                    pack_split_h(c[i][j][rr*2+0] * sc, c[i][j][rr*2+1] * sc, ph, pl);
                    *(uint32_t*)(dh_ + off) = ph;
                    *(uint32_t*)(dl_ + off) = pl;
                }
            }
        }
    } else {
        #pragma unroll
        for (int i = 0; i < 4; i++) {
            const int r0g = m0 + wm + i * 16 + g;
            #pragma unroll
            for (int j = 0; j < 8; j++) {
                const int col = n0 + wn + j * 8 + tig * 2;
                #pragma unroll
                for (int rr = 0; rr < 2; rr++) {
                    const int row = r0g + rr * 8;
                    *(float2*)(Cout + (size_t)row * DIM + col) =
                        make_float2(c[i][j][rr*2+0], c[i][j][rr*2+1]);
                }
            }
        }
    }
}

// ===================== 3) flash attention: QK 3-term, PV 2-term ==============
// stage (32768 B): KH@0, KL@8192, VH@16384, VL@24576
#define AST 32768
__device__ __forceinline__ void kv_load(uint32_t sb, int st, size_t kvbase,
                                        int kt, int tid) {
    const int r  = tid >> 1;
    const int c0 = (tid & 1) * 4;
    const uint32_t base = sb + st * AST;
    #pragma unroll
    for (int it = 0; it < 4; it++) {
        const int ch = c0 + it;
        const uint32_t d = base + sw128(r, ch * 16);
        const size_t src = kvbase + (size_t)(kt * 64 + r) * DH + ch * 8;
        cp16(d,         g_kh + src);
        cp16(d + 8192,  g_kl + src);
        cp16(d + 16384, g_vh + src);
        cp16(d + 24576, g_vl + src);
    }
}

__global__ void __launch_bounds__(128, 2) attn_kernel() {
    extern __shared__ char dsm[];
    const uint32_t sb = smem_u32(dsm);
    const int qt = (int)gridDim.x - 1 - (int)blockIdx.x;  // big tiles first
    const int bh = blockIdx.y, b = bh >> 3, h = bh & 7;
    const int tid = threadIdx.x, lane = tid & 31, warp = tid >> 5;
    const int g = lane >> 2, tig = lane & 3;
    const int wm = warp * 32;
    const size_t kvbase = (size_t)bh * NSEQ * DH;

    // ---- stage Q into stage-1/2 areas ----
    const size_t qbase = ((size_t)bh * NSEQ + qt * 128) * DH;
    for (int i = tid; i < 1024; i += 128) {
        const int r = i >> 3, cch = i & 7;
        const uint32_t d = sw128(r, cch * 16);
        const size_t src = qbase + (size_t)r * DH + cch * 8;
        *(uint4*)(dsm + 32768 + d) = *(const uint4*)(g_qh + src);
        *(uint4*)(dsm + 65536 + d) = *(const uint4*)(g_ql + src);
    }
    __syncthreads();
    uint32_t qh[2][4][4], ql[2][4][4];
    #pragma unroll
    for (int mf = 0; mf < 2; mf++)
        #pragma unroll
        for (int kk = 0; kk < 4; kk++) {
            const int r  = wm + mf * 16 + (lane & 15);
            const int cb = kk * 32 + (lane >> 4) * 16;
            const uint32_t off = sw128(r, cb);
            ldsm4(qh[mf][kk], sb + 32768 + off);
            ldsm4(ql[mf][kk], sb + 65536 + off);
        }
    __syncthreads();

    const int ktmax = 2 * qt + 1;
    kv_load(sb, 0, kvbase, 0, tid);
    CP_COMMIT();
    kv_load(sb, 1, kvbase, 1, tid);
    CP_COMMIT();

    float o[2][8][4] = {};
    float mv[4] = {-1e30f, -1e30f, -1e30f, -1e30f};
    float lv[4] = {0.f, 0.f, 0.f, 0.f};

    int stc = 0, stp = 2;
    for (int kt = 0; kt <= ktmax; kt++) {
        CP_WAIT1();
        __syncthreads();
        if (kt + 2 <= ktmax)
            kv_load(sb, stp, kvbase, kt + 2, tid);
        CP_COMMIT();

        const uint32_t uK  = sb + stc * AST;
        const uint32_t uKl = uK + 8192;
        const uint32_t uV  = uK + 16384;
        const uint32_t uVl = uK + 24576;

        // ---- S = Q K^T (3-term fp16), log2 domain ----
        float s[2][8][4] = {};
        #pragma unroll
        for (int kk = 0; kk < 4; kk++) {
            const int cb = kk * 32 + (lane >> 4) * 16;
            #pragma unroll
            for (int np = 0; np < 2; np++) {
                const int nb0 = np * 2, nb1 = np * 2 + 1;
                const int r0 = nb0 * 16 + (lane & 7) + ((lane >> 3) & 1) * 8;
                const int r1 = nb1 * 16 + (lane & 7) + ((lane >> 3) & 1) * 8;
                uint32_t kh0[4], kl0[4], kh1[4], kl1[4];
                ldsm4(kh0, uK  + sw128(r0, cb));
                ldsm4(kl0, uKl + sw128(r0, cb));
                ldsm4(kh1, uK  + sw128(r1, cb));
                ldsm4(kl1, uKl + sw128(r1, cb));
                #pragma unroll
                for (int mf = 0; mf < 2; mf++) {
                    mma16816(s[mf][nb0*2+0], qh[mf][kk], kh0[0], kh0[2]);
                    mma16816(s[mf][nb0*2+1], qh[mf][kk], kh0[1], kh0[3]);
                    mma16816(s[mf][nb1*2+0], qh[mf][kk], kh1[0], kh1[2]);
                    mma16816(s[mf][nb1*2+1], qh[mf][kk], kh1[1], kh1[3]);
                    mma16816(s[mf][nb0*2+0], qh[mf][kk], kl0[0], kl0[2]);
                    mma16816(s[mf][nb0*2+1], qh[mf][kk], kl0[1], kl0[3]);
                    mma16816(s[mf][nb1*2+0], qh[mf][kk], kl1[0], kl1[2]);
                    mma16816(s[mf][nb1*2+1], qh[mf][kk], kl1[1], kl1[3]);
                    mma16816(s[mf][nb0*2+0], ql[mf][kk], kh0[0], kh0[2]);
                    mma16816(s[mf][nb0*2+1], ql[mf][kk], kh0[1], kh0[3]);
                    mma16816(s[mf][nb1*2+0], ql[mf][kk], kh1[0], kh1[2]);
                    mma16816(s[mf][nb1*2+1], ql[mf][kk], kh1[1], kh1[3]);
                }
            }
        }
        // ---- causal mask (diagonal tiles only) ----
        if (kt >= 2 * qt) {
            #pragma unroll
            for (int mf = 0; mf < 2; mf++) {
                const int row0 = qt * 128 + wm + mf * 16 + g;
                #pragma unroll
                for (int j = 0; j < 8; j++) {
                    const int col = kt * 64 + j * 8 + tig * 2;
                    if (col     > row0)     s[mf][j][0] = -1e30f;
                    if (col + 1 > row0)     s[mf][j][1] = -1e30f;
                    if (col     > row0 + 8) s[mf][j][2] = -1e30f;
                    if (col + 1 > row0 + 8) s[mf][j][3] = -1e30f;
                }
            }
        }
        // ---- row max ----
        float mx[4] = {-1e30f, -1e30f, -1e30f, -1e30f};
        #pragma unroll
        for (int mf = 0; mf < 2; mf++)
            #pragma unroll
            for (int j = 0; j < 8; j++) {
                mx[mf*2+0] = fmaxf(mx[mf*2+0], fmaxf(s[mf][j][0], s[mf][j][1]));
                mx[mf*2+1] = fmaxf(mx[mf*2+1], fmaxf(s[mf][j][2], s[mf][j][3]));
            }
        #pragma unroll
        for (int i = 0; i < 4; i++) {
            mx[i] = fmaxf(mx[i], __shfl_xor_sync(0xffffffffu, mx[i], 1));
            mx[i] = fmaxf(mx[i], __shfl_xor_sync(0xffffffffu, mx[i], 2));
        }
        if (mx[0] > mv[0] || mx[1] > mv[1] || mx[2] > mv[2] || mx[3] > mv[3]) {
            float cor[4];
            #pragma unroll
            for (int i = 0; i < 4; i++) {
                const float mn = fmaxf(mv[i], mx[i]);
                cor[i] = ex2(mv[i] - mn);
                lv[i] *= cor[i];
                mv[i] = mn;
            }
            #pragma unroll
            for (int mf = 0; mf < 2; mf++)
                #pragma unroll
                for (int j = 0; j < 8; j++) {
                    o[mf][j][0] *= cor[mf*2+0]; o[mf][j][1] *= cor[mf*2+0];
                    o[mf][j][2] *= cor[mf*2+1]; o[mf][j][3] *= cor[mf*2+1];
                }
        }
        // ---- exp + pack (fp16 P, no residual) + PV 2-term ----
        float ls[4] = {0.f, 0.f, 0.f, 0.f};
        #pragma unroll
        for (int kk = 0; kk < 4; kk++) {
            const int r = kk * 16 + (lane & 7) + ((lane >> 4) << 3);
            uint32_t pah[2][4];
            #pragma unroll
            for (int mf = 0; mf < 2; mf++) {
                float p0 = ex2(s[mf][2*kk  ][0] - mv[mf*2+0]);
                float p1 = ex2(s[mf][2*kk  ][1] - mv[mf*2+0]);
                float p2 = ex2(s[mf][2*kk  ][2] - mv[mf*2+1]);
                float p3 = ex2(s[mf][2*kk  ][3] - mv[mf*2+1]);
                float p4 = ex2(s[mf][2*kk+1][0] - mv[mf*2+0]);
                float p5 = ex2(s[mf][2*kk+1][1] - mv[mf*2+0]);
                float p6 = ex2(s[mf][2*kk+1][2] - mv[mf*2+1]);
                float p7 = ex2(s[mf][2*kk+1][3] - mv[mf*2+1]);
                ls[mf*2+0] += (p0 + p1) + (p4 + p5);
                ls[mf*2+1] += (p2 + p3) + (p6 + p7);
                pack2h(p0, p1, pah[mf][0]);
                pack2h(p2, p3, pah[mf][1]);
                pack2h(p4, p5, pah[mf][2]);
                pack2h(p6, p7, pah[mf][3]);
            }
            #pragma unroll
            for (int half = 0; half < 2; half++) {
                uint32_t vh0[4], vl0[4], vh1[4], vl1[4];
                const int nb0 = half * 2, nb1 = half * 2 + 1;
                const int cb0 = nb0 * 32 + ((lane >> 3) & 1) * 16;
                const int cb1 = nb1 * 32 + ((lane >> 3) & 1) * 16;
                ldsm4t(vh0, uV  + sw128(r, cb0));
                ldsm4t(vl0, uVl + sw128(r, cb0));
                ldsm4t(vh1, uV  + sw128(r, cb1));
                ldsm4t(vl1, uVl + sw128(r, cb1));
                #pragma unroll
                for (int mf = 0; mf < 2; mf++) {
                    mma16816(o[mf][nb0*2+0], pah[mf], vh0[0], vh0[2]);
                    mma16816(o[mf][nb0*2+1], pah[mf], vh0[1], vh0[3]);
                    mma16816(o[mf][nb1*2+0], pah[mf], vh1[0], vh1[2]);
                    mma16816(o[mf][nb1*2+1], pah[mf], vh1[1], vh1[3]);
                    mma16816(o[mf][nb0*2+0], pah[mf], vl0[0], vl0[2]);
                    mma16816(o[mf][nb0*2+1], pah[mf], vl0[1], vl0[3]);
                    mma16816(o[mf][nb1*2+0], pah[mf], vl1[0], vl1[2]);
                    mma16816(o[mf][nb1*2+1], pah[mf], vl1[1], vl1[3]);
                }
            }
        }
        #pragma unroll
        for (int i = 0; i < 4; i++) {
            ls[i] += __shfl_xor_sync(0xffffffffu, ls[i], 1);
            ls[i] += __shfl_xor_sync(0xffffffffu, ls[i], 2);
            lv[i] += ls[i];
        }

        stc = (stc == 2) ? 0 : stc + 1;
        stp = (stp == 2) ? 0 : stp + 1;
    }

    // ---- epilogue (hi only) ----
    float inv[4];
    #pragma unroll
    for (int i = 0; i < 4; i++) inv[i] = 1.0f / (lv[i] + 1e-10f);
    #pragma unroll
    for (int mf = 0; mf < 2; mf++) {
        const int row0 = qt * 128 + wm + mf * 16 + g;
        #pragma unroll
        for (int j = 0; j < 8; j++) {
            const int col = h * DH + j * 8 + tig * 2;
            {
                const size_t off = (size_t)(b * NSEQ + row0) * AO_N + col;
                uint32_t ph;
                pack2h(o[mf][j][0] * inv[mf*2+0], o[mf][j][1] * inv[mf*2+0], ph);
                *(uint32_t*)(g_ao_hi + off) = ph;
            }
            {
                const size_t off = (size_t)(b * NSEQ + row0 + 8) * AO_N + col;
                uint32_t ph;
                pack2h(o[mf][j][2] * inv[mf*2+1], o[mf][j][3] * inv[mf*2+1], ph);
                *(uint32_t*)(g_ao_hi + off) = ph;
            }
        }
    }
}

// ===================== launch ================================================
extern "C" void kernel_launch(void* const* d_in, const int* in_sizes, int n_in,
                              void* d_out, int out_size) {
    const float* x     = (const float*)d_in[0];
    const float* gamma = (const float*)d_in[1];
    const float* beta  = (const float*)d_in[2];
    const float* wqkv  = (const float*)d_in[3];
    const float* wout  = (const float*)d_in[4];
    float* out = (float*)d_out;

    cudaFuncSetAttribute(gemm_mma<0>, cudaFuncAttributeMaxDynamicSharedMemorySize, 3 * GSTAGE);
    cudaFuncSetAttribute(gemm_mma<1>, cudaFuncAttributeMaxDynamicSharedMemorySize, 3 * GSTAGE);
    cudaFuncSetAttribute(attn_kernel, cudaFuncAttributeMaxDynamicSharedMemorySize, 3 * AST);

    prep_kernel<<<TOKENS + CONV0_BLKS + CONV1_BLKS, 256>>>(x, gamma, beta, wqkv, wout);
    gemm_mma<0><<<dim3(QKV_N / 128, TOKENS / 128), 128, 3 * GSTAGE>>>(nullptr);
    attn_kernel<<<dim3(NSEQ / 128, BH_N), 128, 3 * AST>>>();
    gemm_mma<1><<<dim3(DIM / 128, TOKENS / 128), 128, 3 * GSTAGE>>>(out);
}